// round 3
// baseline (speedup 1.0000x reference)
#include <cuda_runtime.h>
#include <cuda_bf16.h>
#include <math.h>

// Problem constants
#define NN   10000          // nodes
#define EE   160000         // edges
#define TT   12             // seq len
#define FF   256            // features
#define NF   (NN * FF)      // floats per [N,F] matrix
#define NC_GRU 512          // u|c interleaved columns
#define WSZ  (1024 * 512)   // packed weight size per (net,layer)

// ---------------------------------------------------------------------------
// Static device scratch (no allocations allowed; referenced directly, no
// cudaGetSymbolAddress anywhere)
// ---------------------------------------------------------------------------
__device__ float g_h[4 * NF];          // h buffers: idx = buf*2+layer (ping-pong)
__device__ float g_ax[NF];             // neighbor-mean of layer input
__device__ float g_ah[NF];             // neighbor-mean of h
__device__ float g_Wpack[4 * WSZ];     // packed [1024,512] weights: encL0,encL1,decL0,decL1
__device__ float g_bpack[4 * 512];     // packed biases (bx+bh, u/c interleaved)
__device__ int   g_deg[NN];
__device__ float g_dinv[NN];
__device__ int   g_rowptr[NN + 1];
__device__ int   g_cursor[NN];
__device__ int   g_col[EE];            // CSR col indices (src nodes) grouped by dst

// Source-operand codes: 0..3 -> g_h quarter, 4 -> g_ax, 5 -> g_ah, 6 -> external x
__device__ __forceinline__ const float* srcPtr(int code, const float* xext) {
    if (code < 4) return g_h + (size_t)code * NF;
    if (code == 4) return g_ax;
    if (code == 5) return g_ah;
    return xext;
}

// ---------------------------------------------------------------------------
// Prep kernels
// ---------------------------------------------------------------------------
__global__ void zero_kernel() {
    int i = blockIdx.x * 256 + threadIdx.x;
    if (i < 4 * NF) g_h[i] = 0.0f;
    if (i < NN) g_deg[i] = 0;
}

__global__ void deg_kernel(const int* __restrict__ dst) {
    int e = blockIdx.x * 256 + threadIdx.x;
    if (e < EE) atomicAdd(&g_deg[dst[e]], 1);
}

// Single-block scan over g_deg -> rowptr, cursor, dinv
__global__ void scan_kernel() {
    __shared__ int ssum[1024];
    int tid = threadIdx.x;
    int local[10];
    int s = 0;
#pragma unroll
    for (int i = 0; i < 10; i++) {
        int idx = tid * 10 + i;
        int v = (idx < NN) ? g_deg[idx] : 0;
        local[i] = s;
        s += v;
    }
    ssum[tid] = s;
    __syncthreads();
    for (int off = 1; off < 1024; off <<= 1) {
        int v = (tid >= off) ? ssum[tid - off] : 0;
        __syncthreads();
        ssum[tid] += v;
        __syncthreads();
    }
    int base = (tid > 0) ? ssum[tid - 1] : 0;
#pragma unroll
    for (int i = 0; i < 10; i++) {
        int idx = tid * 10 + i;
        if (idx < NN) {
            int rp = base + local[i];
            g_rowptr[idx] = rp;
            g_cursor[idx] = rp;
            int d = g_deg[idx];
            g_dinv[idx] = (d > 0) ? (1.0f / (float)d) : 0.0f;
        }
    }
    if (tid == 1023) g_rowptr[NN] = ssum[1023];
}

__global__ void fill_kernel(const int* __restrict__ src, const int* __restrict__ dst) {
    int e = blockIdx.x * 256 + threadIdx.x;
    if (e >= EE) return;
    int d = dst[e];
    int p = atomicAdd(&g_cursor[d], 1);
    g_col[p] = src[e];
}

// Pack 4 weight matrices [F,3F] -> one [1024,512] (K blocks: x|ax|h|ah),
// keeping only u (cols F..2F) and c (cols 2F..3F), interleaved:
// n=2f -> u_f, n=2f+1 -> c_f.
__global__ void pack_kernel(int set,
                            const float* __restrict__ Wxs, const float* __restrict__ Wxn,
                            const float* __restrict__ Whs, const float* __restrict__ Whn,
                            const float* __restrict__ bx, const float* __restrict__ bh) {
    int idx = blockIdx.x * 256 + threadIdx.x;
    if (idx >= WSZ) return;
    int k = idx >> 9;         // 0..1023
    int n = idx & 511;        // 0..511
    int kb = k >> 8;          // which source matrix
    int kin = k & 255;        // row within source
    const float* M = (kb == 0) ? Wxs : (kb == 1) ? Wxn : (kb == 2) ? Whs : Whn;
    int f = n >> 1;
    int scol = (n & 1) ? (2 * FF + f) : (FF + f);
    g_Wpack[set * WSZ + idx] = M[kin * (3 * FF) + scol];
    if (k == 0) g_bpack[set * 512 + n] = bx[scol] + bh[scol];
}

// ---------------------------------------------------------------------------
// Neighbor-mean aggregation: per-node CSR gather, float4 vectorized
// ---------------------------------------------------------------------------
template <bool WITHX>
__global__ void agg_kernel(const float* __restrict__ xext, int codeInp, int codeH) {
    const float* inp  = srcPtr(codeInp, xext);
    const float* hsrc = srcPtr(codeH, xext);
    int node = blockIdx.x;
    int f4 = threadIdx.x;  // 0..63, each handles 4 floats
    int e0 = g_rowptr[node];
    int e1 = g_rowptr[node + 1];
    float4 sx = make_float4(0.f, 0.f, 0.f, 0.f);
    float4 sh = make_float4(0.f, 0.f, 0.f, 0.f);
    for (int e = e0; e < e1; ++e) {
        int s = g_col[e];
        float4 hv = ((const float4*)(hsrc + (size_t)s * FF))[f4];
        sh.x += hv.x; sh.y += hv.y; sh.z += hv.z; sh.w += hv.w;
        if (WITHX) {
            float4 xv = ((const float4*)(inp + (size_t)s * FF))[f4];
            sx.x += xv.x; sx.y += xv.y; sx.z += xv.z; sx.w += xv.w;
        }
    }
    float di = g_dinv[node];
    ((float4*)(g_ah + (size_t)node * FF))[f4] =
        make_float4(sh.x * di, sh.y * di, sh.z * di, sh.w * di);
    if (WITHX)
        ((float4*)(g_ax + (size_t)node * FF))[f4] =
            make_float4(sx.x * di, sx.y * di, sx.z * di, sx.w * di);
}

// ---------------------------------------------------------------------------
// Fused GEMM (+GRU or +bias epilogue).
//   C[M, NC] = sum_k A_{k>>8}[m, k&255] * W[k, n]
// GRU epilogue: u = sigmoid(C[:,2f]+b), c = tanh(C[:,2f+1]+b), hnew = u*h+(1-u)*c
// set >= 0 selects packed weights/bias; set < 0 uses Wext/bExt.
// outIdx >= 0 writes g_h quarter; outIdx < 0 writes outExt.
// ---------------------------------------------------------------------------
#define BM 128
#define BN 128
#define BK 8

template <int NC, bool GRU>
__global__ __launch_bounds__(256)
void gemm_kernel(const float* __restrict__ xext,
                 int c0, int c1, int c2, int c3,
                 const float* __restrict__ Wext, const float* __restrict__ bExt,
                 int set, int holdIdx, float* __restrict__ outExt, int outIdx,
                 int kstart, int ktot) {
    __shared__ float As[BK][BM];
    __shared__ float Bs[BK][BN];
    const int tid = threadIdx.x;
    const int bm = blockIdx.x * BM;
    const int bn = blockIdx.y * BN;

    const float* Aptr[4] = {srcPtr(c0, xext), srcPtr(c1, xext),
                            srcPtr(c2, xext), srcPtr(c3, xext)};
    const float* W    = (set >= 0) ? (g_Wpack + (size_t)set * WSZ) : Wext;
    const float* bias = (set >= 0) ? (g_bpack + set * 512) : bExt;
    const float* hold = g_h + (size_t)((holdIdx >= 0) ? holdIdx : 0) * NF;
    float* out = (outIdx >= 0) ? (g_h + (size_t)outIdx * NF) : outExt;

    const int arow = tid >> 1;          // 0..127
    const int acol = (tid & 1) << 2;    // 0 or 4
    const int brow = tid >> 5;          // 0..7
    const int bcol = (tid & 31) << 2;   // 0..124
    const int ty = tid >> 4;            // 0..15
    const int tx = tid & 15;            // 0..15

    float acc[8][8];
#pragma unroll
    for (int i = 0; i < 8; i++)
#pragma unroll
        for (int j = 0; j < 8; j++) acc[i][j] = 0.0f;

    for (int k0 = kstart; k0 < ktot; k0 += BK) {
        const float* A = Aptr[k0 >> 8];
        int kin = (k0 & 255) + acol;
        float4 av = make_float4(0.f, 0.f, 0.f, 0.f);
        int r = bm + arow;
        if (r < NN) av = *(const float4*)(A + (size_t)r * FF + kin);
        As[acol + 0][arow] = av.x;
        As[acol + 1][arow] = av.y;
        As[acol + 2][arow] = av.z;
        As[acol + 3][arow] = av.w;
        float4 bv = *(const float4*)(W + (size_t)(k0 + brow) * NC + bn + bcol);
        *(float4*)&Bs[brow][bcol] = bv;
        __syncthreads();
#pragma unroll
        for (int kk = 0; kk < BK; kk++) {
            float4 a0 = *(const float4*)&As[kk][ty * 8];
            float4 a1 = *(const float4*)&As[kk][ty * 8 + 4];
            float4 b0 = *(const float4*)&Bs[kk][tx * 8];
            float4 b1 = *(const float4*)&Bs[kk][tx * 8 + 4];
            float a[8] = {a0.x, a0.y, a0.z, a0.w, a1.x, a1.y, a1.z, a1.w};
            float b[8] = {b0.x, b0.y, b0.z, b0.w, b1.x, b1.y, b1.z, b1.w};
#pragma unroll
            for (int i = 0; i < 8; i++)
#pragma unroll
                for (int j = 0; j < 8; j++) acc[i][j] += a[i] * b[j];
        }
        __syncthreads();
    }

    const int col0 = bn + tx * 8;
    if (GRU) {
#pragma unroll
        for (int i = 0; i < 8; i++) {
            int r = bm + ty * 8 + i;
            if (r >= NN) break;
#pragma unroll
            for (int j = 0; j < 4; j++) {
                float up = acc[i][2 * j] + bias[col0 + 2 * j];
                float cp = acc[i][2 * j + 1] + bias[col0 + 2 * j + 1];
                float u = 1.0f / (1.0f + expf(-up));
                float c = tanhf(cp);
                int f = (col0 >> 1) + j;
                float hv = hold[(size_t)r * FF + f];
                out[(size_t)r * FF + f] = u * hv + (1.0f - u) * c;
            }
        }
    } else {
#pragma unroll
        for (int i = 0; i < 8; i++) {
            int r = bm + ty * 8 + i;
            if (r >= NN) break;
#pragma unroll
            for (int j = 0; j < 8; j++) {
                out[(size_t)r * FF + col0 + j] = acc[i][j] + bias[col0 + j];
            }
        }
    }
}

// ---------------------------------------------------------------------------
// Host orchestration (graph-capturable: kernel launches only; no runtime API)
// ---------------------------------------------------------------------------
extern "C" void kernel_launch(void* const* d_in, const int* in_sizes, int n_in,
                              void* d_out, int out_size) {
    const float* x    = (const float*)d_in[0];
    const int*   src  = (const int*)d_in[1];
    const int*   dst  = (const int*)d_in[2];
    const float* eWxs = (const float*)d_in[3];
    const float* eWxn = (const float*)d_in[4];
    const float* ebx  = (const float*)d_in[5];
    const float* eWhs = (const float*)d_in[6];
    const float* eWhn = (const float*)d_in[7];
    const float* ebh  = (const float*)d_in[8];
    const float* dWxs = (const float*)d_in[9];
    const float* dWxn = (const float*)d_in[10];
    const float* dbx  = (const float*)d_in[11];
    const float* dWhs = (const float*)d_in[12];
    const float* dWhn = (const float*)d_in[13];
    const float* dbh  = (const float*)d_in[14];
    const float* outW = (const float*)d_in[15];
    const float* outb = (const float*)d_in[16];
    float* out = (float*)d_out;

    const int F3F = FF * 3 * FF;  // per-layer stride inside [L,F,3F]

    zero_kernel<<<(4 * NF + 255) / 256, 256>>>();
    deg_kernel<<<(EE + 255) / 256, 256>>>(dst);
    scan_kernel<<<1, 1024>>>();
    fill_kernel<<<(EE + 255) / 256, 256>>>(src, dst);
    pack_kernel<<<(WSZ + 255) / 256, 256>>>(0, eWxs, eWxn, eWhs, eWhn, ebx, ebh);
    pack_kernel<<<(WSZ + 255) / 256, 256>>>(1, eWxs + F3F, eWxn + F3F, eWhs + F3F,
                                            eWhn + F3F, ebx + 3 * FF, ebh + 3 * FF);
    pack_kernel<<<(WSZ + 255) / 256, 256>>>(2, dWxs, dWxn, dWhs, dWhn, dbx, dbh);
    pack_kernel<<<(WSZ + 255) / 256, 256>>>(3, dWxs + F3F, dWxn + F3F, dWhs + F3F,
                                            dWhn + F3F, dbx + 3 * FF, dbh + 3 * FF);

    dim3 gg((NN + BM - 1) / BM, NC_GRU / BN);  // (79, 4)
    dim3 og((NN + BM - 1) / BM, FF / BN);      // (79, 2)
    int cur0 = 0, cur1 = 0;

    // h-buffer code for (buf, layer) = buf*2 + layer (matches g_h quarters)
    auto HI = [](int buf, int layer) { return buf * 2 + layer; };

    // ---- Encoder ----
    for (int t = 0; t < TT; t++) {
        const float* xt = x + (size_t)t * NF;
        // layer 0: inp = x_t (code 6), h = H(cur0,0)
        agg_kernel<true><<<NN, 64>>>(xt, 6, HI(cur0, 0));
        gemm_kernel<NC_GRU, true><<<gg, 256>>>(xt, 6, 4, HI(cur0, 0), 5,
                                               nullptr, nullptr, 0,
                                               HI(cur0, 0), nullptr, HI(1 - cur0, 0),
                                               0, 1024);
        cur0 ^= 1;
        // layer 1: inp = new h0
        agg_kernel<true><<<NN, 64>>>(nullptr, HI(cur0, 0), HI(cur1, 1));
        gemm_kernel<NC_GRU, true><<<gg, 256>>>(nullptr, HI(cur0, 0), 4, HI(cur1, 1), 5,
                                               nullptr, nullptr, 1,
                                               HI(cur1, 1), nullptr, HI(1 - cur1, 1),
                                               0, 1024);
        cur1 ^= 1;
    }

    // ---- Decoder (layer-0 input is zeros: skip x/ax terms; kstart=512) ----
    for (int t = 0; t < TT; t++) {
        agg_kernel<false><<<NN, 64>>>(nullptr, 0, HI(cur0, 0));
        gemm_kernel<NC_GRU, true><<<gg, 256>>>(nullptr, 0, 0, HI(cur0, 0), 5,
                                               nullptr, nullptr, 2,
                                               HI(cur0, 0), nullptr, HI(1 - cur0, 0),
                                               512, 1024);
        cur0 ^= 1;
        agg_kernel<true><<<NN, 64>>>(nullptr, HI(cur0, 0), HI(cur1, 1));
        gemm_kernel<NC_GRU, true><<<gg, 256>>>(nullptr, HI(cur0, 0), 4, HI(cur1, 1), 5,
                                               nullptr, nullptr, 3,
                                               HI(cur1, 1), nullptr, HI(1 - cur1, 1),
                                               0, 1024);
        cur1 ^= 1;
        // output projection: out_t = h1 @ out_W + out_b
        gemm_kernel<FF, false><<<og, 256>>>(nullptr, HI(cur1, 1), 0, 0, 0,
                                            outW, outb, -1,
                                            -1, out + (size_t)t * NF, -1,
                                            0, 256);
    }
}

// round 6
// speedup vs baseline: 1.9657x; 1.9657x over previous
#include <cuda_runtime.h>
#include <cuda_bf16.h>
#include <math.h>
#include <stdint.h>

// Problem constants
#define NN   10000
#define EE   160000
#define TT   12
#define FF   256
#define NF   (NN * FF)
#define PAD  32768           // row-overflow pad for bf16 A-sources (128 rows * 256)

// ---------------------------------------------------------------------------
// PTX helpers (sm_100-safe subset: mma.sync + ldmatrix + cp.async)
// ---------------------------------------------------------------------------
__device__ __forceinline__ uint32_t smem_u32(const void* p) {
    uint32_t a;
    asm("{ .reg .u64 t; cvta.to.shared.u64 t, %1; cvt.u32.u64 %0, t; }" : "=r"(a) : "l"(p));
    return a;
}
__device__ __forceinline__ void cpasync16(uint32_t s, const void* g) {
    asm volatile("cp.async.ca.shared.global [%0], [%1], 16;" :: "r"(s), "l"(g));
}
#define CP_COMMIT() asm volatile("cp.async.commit_group;" ::: "memory")
#define CP_WAIT1()  asm volatile("cp.async.wait_group 1;" ::: "memory")
#define CP_WAIT0()  asm volatile("cp.async.wait_group 0;" ::: "memory")

#define LDSM4(r0, r1, r2, r3, a) \
    asm volatile("ldmatrix.sync.aligned.m8n8.x4.shared.b16 {%0,%1,%2,%3}, [%4];" \
                 : "=r"(r0), "=r"(r1), "=r"(r2), "=r"(r3) : "r"(a))
#define LDSM2(r0, r1, a) \
    asm volatile("ldmatrix.sync.aligned.m8n8.x2.shared.b16 {%0,%1}, [%2];" \
                 : "=r"(r0), "=r"(r1) : "r"(a))
#define MMA16816(d, a0, a1, a2, a3, b0, b1) \
    asm volatile("mma.sync.aligned.m16n8k16.row.col.f32.bf16.bf16.f32 " \
                 "{%0,%1,%2,%3}, {%4,%5,%6,%7}, {%8,%9}, {%0,%1,%2,%3};" \
                 : "+f"((d)[0]), "+f"((d)[1]), "+f"((d)[2]), "+f"((d)[3]) \
                 : "r"(a0), "r"(a1), "r"(a2), "r"(a3), "r"(b0), "r"(b1))

// ---------------------------------------------------------------------------
// Static device scratch
// ---------------------------------------------------------------------------
__device__ __align__(16) float         g_h[4 * NF];                 // fp32 h quarters
__device__ __align__(16) __nv_bfloat16 g_hhi[4 * NF + PAD];
__device__ __align__(16) __nv_bfloat16 g_hlo[4 * NF + PAD];
__device__ __align__(16) __nv_bfloat16 g_xhi[12 * NF + PAD];
__device__ __align__(16) __nv_bfloat16 g_xlo[12 * NF + PAD];
__device__ __align__(16) __nv_bfloat16 g_axhi[NF + PAD];
__device__ __align__(16) __nv_bfloat16 g_axlo[NF + PAD];
__device__ __align__(16) __nv_bfloat16 g_ahhi[NF + PAD];
__device__ __align__(16) __nv_bfloat16 g_ahlo[NF + PAD];
__device__ __align__(16) __nv_bfloat16 g_Wthi[4 * 512 * 1024];      // [set][n][k] transposed
__device__ __align__(16) __nv_bfloat16 g_Wtlo[4 * 512 * 1024];
__device__ __align__(16) __nv_bfloat16 g_Othi[256 * 256];           // out-proj [n][k]
__device__ __align__(16) __nv_bfloat16 g_Otlo[256 * 256];
__device__ float g_bpack[4 * 512];
__device__ int   g_deg[NN];
__device__ float g_dinv[NN];
__device__ int   g_rowptr[NN + 1];
__device__ int   g_cursor[NN];
__device__ int   g_col[EE];

__device__ __forceinline__ void split_bf16(float v, __nv_bfloat16& hi, __nv_bfloat16& lo) {
    hi = __float2bfloat16(v);
    lo = __float2bfloat16(v - __bfloat162float(hi));
}
__device__ __forceinline__ const float* srcF32(int code, const float* xext) {
    if (code < 4) return g_h + (size_t)code * NF;
    return xext;
}
__device__ __forceinline__ const __nv_bfloat16* srcHi(int code, size_t xoff) {
    if (code < 4) return g_hhi + (size_t)code * NF;
    if (code == 4) return g_axhi;
    if (code == 5) return g_ahhi;
    return g_xhi + xoff;
}
__device__ __forceinline__ const __nv_bfloat16* srcLo(int code, size_t xoff) {
    if (code < 4) return g_hlo + (size_t)code * NF;
    if (code == 4) return g_axlo;
    if (code == 5) return g_ahlo;
    return g_xlo + xoff;
}

// ---------------------------------------------------------------------------
// Prep kernels
// ---------------------------------------------------------------------------
__global__ void zero_kernel() {
    int i = blockIdx.x * 256 + threadIdx.x;
    if (i < 4 * NF) g_h[i] = 0.0f;
    if (i < 4 * NF + PAD) { g_hhi[i] = __float2bfloat16(0.f); g_hlo[i] = __float2bfloat16(0.f); }
    if (i < NN) g_deg[i] = 0;
}

__global__ void xconv_kernel(const float* __restrict__ x) {
    int i = blockIdx.x * 256 + threadIdx.x;
    if (i >= 12 * NF) return;
    __nv_bfloat16 hi, lo;
    split_bf16(x[i], hi, lo);
    g_xhi[i] = hi; g_xlo[i] = lo;
}

__global__ void deg_kernel(const int* __restrict__ dst) {
    int e = blockIdx.x * 256 + threadIdx.x;
    if (e < EE) atomicAdd(&g_deg[dst[e]], 1);
}

__global__ void scan_kernel() {
    __shared__ int ssum[1024];
    int tid = threadIdx.x;
    int local[10];
    int s = 0;
#pragma unroll
    for (int i = 0; i < 10; i++) {
        int idx = tid * 10 + i;
        int v = (idx < NN) ? g_deg[idx] : 0;
        local[i] = s; s += v;
    }
    ssum[tid] = s;
    __syncthreads();
    for (int off = 1; off < 1024; off <<= 1) {
        int v = (tid >= off) ? ssum[tid - off] : 0;
        __syncthreads();
        ssum[tid] += v;
        __syncthreads();
    }
    int base = (tid > 0) ? ssum[tid - 1] : 0;
#pragma unroll
    for (int i = 0; i < 10; i++) {
        int idx = tid * 10 + i;
        if (idx < NN) {
            int rp = base + local[i];
            g_rowptr[idx] = rp; g_cursor[idx] = rp;
            int d = g_deg[idx];
            g_dinv[idx] = (d > 0) ? (1.0f / (float)d) : 0.0f;
        }
    }
    if (tid == 1023) g_rowptr[NN] = ssum[1023];
}

__global__ void fill_kernel(const int* __restrict__ src, const int* __restrict__ dst) {
    int e = blockIdx.x * 256 + threadIdx.x;
    if (e >= EE) return;
    int p = atomicAdd(&g_cursor[dst[e]], 1);
    g_col[p] = src[e];
}

// Transposed+split weight pack: Wt[set][n][k] = M_{k/256}[k%256][scol(n)], n interleaves u/c
__global__ void pack_kernel(int set,
                            const float* __restrict__ Wxs, const float* __restrict__ Wxn,
                            const float* __restrict__ Whs, const float* __restrict__ Whn,
                            const float* __restrict__ bx, const float* __restrict__ bh) {
    int idx = blockIdx.x * 256 + threadIdx.x;
    if (idx >= 512 * 1024) return;
    int n = idx >> 10, k = idx & 1023;
    int kb = k >> 8, kin = k & 255;
    const float* M = (kb == 0) ? Wxs : (kb == 1) ? Wxn : (kb == 2) ? Whs : Whn;
    int f = n >> 1;
    int scol = (n & 1) ? (2 * FF + f) : (FF + f);
    float v = M[kin * (3 * FF) + scol];
    __nv_bfloat16 hi, lo; split_bf16(v, hi, lo);
    size_t o = (size_t)set * (512 * 1024) + idx;
    g_Wthi[o] = hi; g_Wtlo[o] = lo;
    if (k == 0) g_bpack[set * 512 + n] = bx[scol] + bh[scol];
}

__global__ void packO_kernel(const float* __restrict__ outW) {
    int idx = blockIdx.x * 256 + threadIdx.x;
    if (idx >= 256 * 256) return;
    int n = idx >> 8, k = idx & 255;
    __nv_bfloat16 hi, lo; split_bf16(outW[k * 256 + n], hi, lo);
    g_Othi[idx] = hi; g_Otlo[idx] = lo;
}

// ---------------------------------------------------------------------------
// Neighbor-mean aggregation: fp32 gather, bf16 hi/lo output
// ---------------------------------------------------------------------------
template <bool WITHX>
__global__ void agg_kernel(const float* __restrict__ xext, int codeInp, int codeH) {
    const float* inp  = srcF32(codeInp, xext);
    const float* hsrc = srcF32(codeH, xext);
    int node = blockIdx.x;
    int f4 = threadIdx.x;  // 0..63
    int e0 = g_rowptr[node], e1 = g_rowptr[node + 1];
    float4 sx = make_float4(0.f, 0.f, 0.f, 0.f);
    float4 sh = make_float4(0.f, 0.f, 0.f, 0.f);
    for (int e = e0; e < e1; ++e) {
        int s = g_col[e];
        float4 hv = ((const float4*)(hsrc + (size_t)s * FF))[f4];
        sh.x += hv.x; sh.y += hv.y; sh.z += hv.z; sh.w += hv.w;
        if (WITHX) {
            float4 xv = ((const float4*)(inp + (size_t)s * FF))[f4];
            sx.x += xv.x; sx.y += xv.y; sx.z += xv.z; sx.w += xv.w;
        }
    }
    float di = g_dinv[node];
    size_t base = (size_t)node * FF + f4 * 4;
    float vh[4] = {sh.x * di, sh.y * di, sh.z * di, sh.w * di};
#pragma unroll
    for (int i = 0; i < 4; i++) {
        __nv_bfloat16 hi, lo; split_bf16(vh[i], hi, lo);
        g_ahhi[base + i] = hi; g_ahlo[base + i] = lo;
    }
    if (WITHX) {
        float vx[4] = {sx.x * di, sx.y * di, sx.z * di, sx.w * di};
#pragma unroll
        for (int i = 0; i < 4; i++) {
            __nv_bfloat16 hi, lo; split_bf16(vx[i], hi, lo);
            g_axhi[base + i] = hi; g_axlo[base + i] = lo;
        }
    }
}

// ---------------------------------------------------------------------------
// bf16 mma.sync GEMM (3-product split) with fused GRU / bias epilogue.
//   C[128, 128] per CTA; K over {hh, lh, hl} x nblk sources x 8 chunks of 32.
//   B operand = transposed weights [N][K] (col-major for row.col mma).
// ---------------------------------------------------------------------------
#define SROW 40   // smem row stride in bf16 (80 B): conflict-free ldmatrix

__global__ __launch_bounds__(256)
void mma_gemm(int4 codes, int nblk, int xoff_i,
              int wset, int kofs,
              const float* __restrict__ bExt,
              int holdIdx, int outIdx, float* __restrict__ outExt,
              int gruFlag) {
    __shared__ __align__(16) __nv_bfloat16 sA[2][128 * SROW];
    __shared__ __align__(16) __nv_bfloat16 sB[2][128 * SROW];

    const int tid = threadIdx.x;
    const int lane = tid & 31;
    const int wid = tid >> 5;
    const int warp_m = wid & 1;        // 0..1 (64 rows)
    const int warp_n = wid >> 1;       // 0..3 (32 cols)
    const int bm = blockIdx.x * 128;
    const int n0 = blockIdx.y * 128;
    const size_t xoff = (size_t)xoff_i * NF;

    const __nv_bfloat16* Ahi[4];
    const __nv_bfloat16* Alo[4];
    {
        int ca[4] = {codes.x, codes.y, codes.z, codes.w};
#pragma unroll
        for (int b = 0; b < 4; b++) { Ahi[b] = srcHi(ca[b], xoff); Alo[b] = srcLo(ca[b], xoff); }
    }
    const __nv_bfloat16* Whi;
    const __nv_bfloat16* Wlo;
    int kstride;
    const float* bias;
    if (wset >= 0) {
        Whi = g_Wthi + (size_t)wset * (512 * 1024) + kofs;
        Wlo = g_Wtlo + (size_t)wset * (512 * 1024) + kofs;
        kstride = 1024;
        bias = g_bpack + wset * 512;
    } else {
        Whi = g_Othi; Wlo = g_Otlo; kstride = 256; bias = bExt;
    }
    const float* hold = g_h + (size_t)((holdIdx >= 0) ? holdIdx : 0) * NF;

    const uint32_t sAb = smem_u32(&sA[0][0]);
    const uint32_t sBb = smem_u32(&sB[0][0]);
    const uint32_t bufBytes = 128 * SROW * 2;

    float acc[4][4][4];
#pragma unroll
    for (int mi = 0; mi < 4; mi++)
#pragma unroll
        for (int ni = 0; ni < 4; ni++)
#pragma unroll
            for (int v = 0; v < 4; v++) acc[mi][ni][v] = 0.0f;

    // per-thread load mapping: 2 chunks each for A and B
    const int c0 = tid, c1 = tid + 256;   // chunk ids 0..511: row=c>>2, seg=c&3
    const int S = 3 * nblk * 8;

    auto issue = [&](int s, int b) {
        const int pass = s / (nblk * 8);
        const int rem  = s - pass * (nblk * 8);
        const int blk  = rem >> 3;
        const int kc   = rem & 7;
        const __nv_bfloat16* Asrc = (pass == 1) ? Alo[blk] : Ahi[blk];
        const __nv_bfloat16* Bsrc = (pass == 2) ? Wlo : Whi;
        const uint32_t aBase = sAb + b * bufBytes;
        const uint32_t bBase = sBb + b * bufBytes;
#pragma unroll
        for (int j = 0; j < 2; j++) {
            int c = (j == 0) ? c0 : c1;
            int row = c >> 2, seg = c & 3;
            cpasync16(aBase + row * (SROW * 2) + seg * 16,
                      Asrc + ((size_t)(bm + row) << 8) + kc * 32 + seg * 8);
            cpasync16(bBase + row * (SROW * 2) + seg * 16,
                      Bsrc + (size_t)(n0 + row) * kstride + blk * 256 + kc * 32 + seg * 8);
        }
    };

    // ldmatrix per-lane address pieces
    const int selA = lane >> 3;                       // 0..3
    const int rowA = (selA & 1) * 8 + (lane & 7);     // within m16
    const int kpaA = (selA >> 1) * 8;                 // 0 or 8
    const int selB = (lane >> 3) & 1;
    const int rowB = lane & 7;
    const int kpaB = selB * 8;

    issue(0, 0);
    CP_COMMIT();

    for (int s = 0; s < S; s++) {
        const int b = s & 1;
        if (s + 1 < S) { issue(s + 1, 1 - b); CP_COMMIT(); CP_WAIT1(); }
        else           { CP_WAIT0(); }
        __syncthreads();

        const uint32_t aBase = sAb + b * bufBytes;
        const uint32_t bBase = sBb + b * bufBytes;
#pragma unroll
        for (int kh = 0; kh < 2; kh++) {
            uint32_t af[4][4], bf[4][2];
#pragma unroll
            for (int mi = 0; mi < 4; mi++) {
                uint32_t addr = aBase +
                    (warp_m * 64 + mi * 16 + rowA) * (SROW * 2) + (kh * 16 + kpaA) * 2;
                LDSM4(af[mi][0], af[mi][1], af[mi][2], af[mi][3], addr);
            }
#pragma unroll
            for (int ni = 0; ni < 4; ni++) {
                uint32_t addr = bBase +
                    (warp_n * 32 + ni * 8 + rowB) * (SROW * 2) + (kh * 16 + kpaB) * 2;
                LDSM2(bf[ni][0], bf[ni][1], addr);
            }
#pragma unroll
            for (int mi = 0; mi < 4; mi++)
#pragma unroll
                for (int ni = 0; ni < 4; ni++)
                    MMA16816(acc[mi][ni], af[mi][0], af[mi][1], af[mi][2], af[mi][3],
                             bf[ni][0], bf[ni][1]);
        }
        __syncthreads();
    }

    // Epilogue straight from registers
    const int r4 = lane >> 2;          // 0..7
    const int cp2 = (lane & 3) * 2;    // 0,2,4,6
#pragma unroll
    for (int mi = 0; mi < 4; mi++) {
        int row0 = bm + warp_m * 64 + mi * 16 + r4;
#pragma unroll
        for (int ni = 0; ni < 4; ni++) {
            int colp = n0 + warp_n * 32 + ni * 8 + cp2;
#pragma unroll
            for (int half = 0; half < 2; half++) {
                int r = row0 + half * 8;
                if (r >= NN) continue;
                float v0 = acc[mi][ni][half * 2 + 0];
                float v1 = acc[mi][ni][half * 2 + 1];
                if (gruFlag) {
                    float up = v0 + bias[colp];
                    float cc = tanhf(v1 + bias[colp + 1]);
                    float u  = 1.0f / (1.0f + expf(-up));
                    int f = colp >> 1;
                    float hv = hold[(size_t)r * FF + f];
                    float hn = u * hv + (1.0f - u) * cc;
                    size_t o = (size_t)outIdx * NF + (size_t)r * FF + f;
                    g_h[o] = hn;
                    __nv_bfloat16 hi, lo; split_bf16(hn, hi, lo);
                    g_hhi[o] = hi; g_hlo[o] = lo;
                } else {
                    size_t o = (size_t)r * FF + colp;
                    outExt[o]     = v0 + bias[colp];
                    outExt[o + 1] = v1 + bias[colp + 1];
                }
            }
        }
    }
}

// ---------------------------------------------------------------------------
// Host orchestration (graph-capturable)
// ---------------------------------------------------------------------------
extern "C" void kernel_launch(void* const* d_in, const int* in_sizes, int n_in,
                              void* d_out, int out_size) {
    const float* x    = (const float*)d_in[0];
    const int*   src  = (const int*)d_in[1];
    const int*   dst  = (const int*)d_in[2];
    const float* eWxs = (const float*)d_in[3];
    const float* eWxn = (const float*)d_in[4];
    const float* ebx  = (const float*)d_in[5];
    const float* eWhs = (const float*)d_in[6];
    const float* eWhn = (const float*)d_in[7];
    const float* ebh  = (const float*)d_in[8];
    const float* dWxs = (const float*)d_in[9];
    const float* dWxn = (const float*)d_in[10];
    const float* dbx  = (const float*)d_in[11];
    const float* dWhs = (const float*)d_in[12];
    const float* dWhn = (const float*)d_in[13];
    const float* dbh  = (const float*)d_in[14];
    const float* outW = (const float*)d_in[15];
    const float* outb = (const float*)d_in[16];
    float* out = (float*)d_out;

    const int F3F = FF * 3 * FF;

    zero_kernel<<<(4 * NF + PAD + 255) / 256, 256>>>();
    xconv_kernel<<<(12 * NF + 255) / 256, 256>>>(x);
    deg_kernel<<<(EE + 255) / 256, 256>>>(dst);
    scan_kernel<<<1, 1024>>>();
    fill_kernel<<<(EE + 255) / 256, 256>>>(src, dst);
    pack_kernel<<<(512 * 1024 + 255) / 256, 256>>>(0, eWxs, eWxn, eWhs, eWhn, ebx, ebh);
    pack_kernel<<<(512 * 1024 + 255) / 256, 256>>>(1, eWxs + F3F, eWxn + F3F, eWhs + F3F,
                                                   eWhn + F3F, ebx + 3 * FF, ebh + 3 * FF);
    pack_kernel<<<(512 * 1024 + 255) / 256, 256>>>(2, dWxs, dWxn, dWhs, dWhn, dbx, dbh);
    pack_kernel<<<(512 * 1024 + 255) / 256, 256>>>(3, dWxs + F3F, dWxn + F3F, dWhs + F3F,
                                                   dWhn + F3F, dbx + 3 * FF, dbh + 3 * FF);
    packO_kernel<<<(256 * 256 + 255) / 256, 256>>>(outW);

    dim3 gg(79, 4);   // GRU GEMM: 512 cols
    dim3 og(79, 2);   // out-proj: 256 cols
    int cur0 = 0, cur1 = 0;
    auto HI = [](int buf, int layer) { return buf * 2 + layer; };

    // ---- Encoder ----
    for (int t = 0; t < TT; t++) {
        const float* xt = x + (size_t)t * NF;
        agg_kernel<true><<<NN, 64>>>(xt, 6, HI(cur0, 0));
        mma_gemm<<<gg, 256>>>(make_int4(6, 4, HI(cur0, 0), 5), 4, t,
                              0, 0, nullptr, HI(cur0, 0), HI(1 - cur0, 0), nullptr, 1);
        cur0 ^= 1;
        agg_kernel<true><<<NN, 64>>>(nullptr, HI(cur0, 0), HI(cur1, 1));
        mma_gemm<<<gg, 256>>>(make_int4(HI(cur0, 0), 4, HI(cur1, 1), 5), 4, 0,
                              1, 0, nullptr, HI(cur1, 1), HI(1 - cur1, 1), nullptr, 1);
        cur1 ^= 1;
    }

    // ---- Decoder ----
    for (int t = 0; t < TT; t++) {
        agg_kernel<false><<<NN, 64>>>(nullptr, 0, HI(cur0, 0));
        mma_gemm<<<gg, 256>>>(make_int4(HI(cur0, 0), 5, 0, 0), 2, 0,
                              2, 512, nullptr, HI(cur0, 0), HI(1 - cur0, 0), nullptr, 1);
        cur0 ^= 1;
        agg_kernel<true><<<NN, 64>>>(nullptr, HI(cur0, 0), HI(cur1, 1));
        mma_gemm<<<gg, 256>>>(make_int4(HI(cur0, 0), 4, HI(cur1, 1), 5), 4, 0,
                              3, 0, nullptr, HI(cur1, 1), HI(1 - cur1, 1), nullptr, 1);
        cur1 ^= 1;
        mma_gemm<<<og, 256>>>(make_int4(HI(cur1, 1), 0, 0, 0), 1, 0,
                              -1, 0, outb, -1, -1, out + (size_t)t * NF, 0);
    }
}

// round 7
// speedup vs baseline: 2.2245x; 1.1317x over previous
#include <cuda_runtime.h>
#include <cuda_bf16.h>
#include <math.h>
#include <stdint.h>

// Problem constants
#define NN   10000
#define EE   160000
#define TT   12
#define FF   256
#define NF   (NN * FF)
#define PAD  32768           // row-overflow pad for bf16 A-sources (128 rows * 256)

// ---------------------------------------------------------------------------
// PTX helpers (sm_100-safe subset: mma.sync + ldmatrix + cp.async)
// ---------------------------------------------------------------------------
__device__ __forceinline__ uint32_t smem_u32(const void* p) {
    uint32_t a;
    asm("{ .reg .u64 t; cvta.to.shared.u64 t, %1; cvt.u32.u64 %0, t; }" : "=r"(a) : "l"(p));
    return a;
}
__device__ __forceinline__ void cpasync16(uint32_t s, const void* g) {
    asm volatile("cp.async.ca.shared.global [%0], [%1], 16;" :: "r"(s), "l"(g));
}
#define CP_COMMIT() asm volatile("cp.async.commit_group;" ::: "memory")
#define CP_WAIT1()  asm volatile("cp.async.wait_group 1;" ::: "memory")
#define CP_WAIT0()  asm volatile("cp.async.wait_group 0;" ::: "memory")

#define LDSM4(r0, r1, r2, r3, a) \
    asm volatile("ldmatrix.sync.aligned.m8n8.x4.shared.b16 {%0,%1,%2,%3}, [%4];" \
                 : "=r"(r0), "=r"(r1), "=r"(r2), "=r"(r3) : "r"(a))
#define LDSM2(r0, r1, a) \
    asm volatile("ldmatrix.sync.aligned.m8n8.x2.shared.b16 {%0,%1}, [%2];" \
                 : "=r"(r0), "=r"(r1) : "r"(a))
#define MMA16816(d, a0, a1, a2, a3, b0, b1) \
    asm volatile("mma.sync.aligned.m16n8k16.row.col.f32.bf16.bf16.f32 " \
                 "{%0,%1,%2,%3}, {%4,%5,%6,%7}, {%8,%9}, {%0,%1,%2,%3};" \
                 : "+f"((d)[0]), "+f"((d)[1]), "+f"((d)[2]), "+f"((d)[3]) \
                 : "r"(a0), "r"(a1), "r"(a2), "r"(a3), "r"(b0), "r"(b1))

// ---------------------------------------------------------------------------
// Static device scratch
// ---------------------------------------------------------------------------
__device__ __align__(16) float         g_h[4 * NF];                 // fp32 h quarters
__device__ __align__(16) __nv_bfloat16 g_hhi[4 * NF + PAD];
__device__ __align__(16) __nv_bfloat16 g_hlo[4 * NF + PAD];
__device__ __align__(16) __nv_bfloat16 g_xhi[12 * NF + PAD];
__device__ __align__(16) __nv_bfloat16 g_xlo[12 * NF + PAD];
__device__ __align__(16) __nv_bfloat16 g_axhi[NF + PAD];
__device__ __align__(16) __nv_bfloat16 g_axlo[NF + PAD];
__device__ __align__(16) __nv_bfloat16 g_ahhi[NF + PAD];
__device__ __align__(16) __nv_bfloat16 g_ahlo[NF + PAD];
__device__ __align__(16) __nv_bfloat16 g_Wthi[4 * 512 * 1024];      // [set][n][k] transposed
__device__ __align__(16) __nv_bfloat16 g_Wtlo[4 * 512 * 1024];
__device__ __align__(16) __nv_bfloat16 g_Othi[256 * 256];           // out-proj [n][k]
__device__ __align__(16) __nv_bfloat16 g_Otlo[256 * 256];
__device__ float g_bpack[4 * 512];
__device__ int   g_deg[NN];
__device__ float g_dinv[NN];
__device__ int   g_rowptr[NN + 1];
__device__ int   g_cursor[NN];
__device__ int   g_col[EE];

__device__ __forceinline__ void split_bf16(float v, __nv_bfloat16& hi, __nv_bfloat16& lo) {
    hi = __float2bfloat16(v);
    lo = __float2bfloat16(v - __bfloat162float(hi));
}
__device__ __forceinline__ const float* srcF32(int code, const float* xext) {
    if (code < 4) return g_h + (size_t)code * NF;
    return xext;
}
__device__ __forceinline__ const __nv_bfloat16* srcHi(int code, size_t xoff) {
    if (code < 4) return g_hhi + (size_t)code * NF;
    if (code == 4) return g_axhi;
    if (code == 5) return g_ahhi;
    return g_xhi + xoff;
}
__device__ __forceinline__ const __nv_bfloat16* srcLo(int code, size_t xoff) {
    if (code < 4) return g_hlo + (size_t)code * NF;
    if (code == 4) return g_axlo;
    if (code == 5) return g_ahlo;
    return g_xlo + xoff;
}

// ---------------------------------------------------------------------------
// Prep kernels
// ---------------------------------------------------------------------------
__global__ void zero_kernel() {
    int i = blockIdx.x * 256 + threadIdx.x;
    if (i < 4 * NF) g_h[i] = 0.0f;
    if (i < 4 * NF + PAD) { g_hhi[i] = __float2bfloat16(0.f); g_hlo[i] = __float2bfloat16(0.f); }
    if (i < NN) g_deg[i] = 0;
}

__global__ void xconv_kernel(const float* __restrict__ x) {
    int i = blockIdx.x * 256 + threadIdx.x;
    if (i >= 12 * NF) return;
    __nv_bfloat16 hi, lo;
    split_bf16(x[i], hi, lo);
    g_xhi[i] = hi; g_xlo[i] = lo;
}

__global__ void deg_kernel(const int* __restrict__ dst) {
    int e = blockIdx.x * 256 + threadIdx.x;
    if (e < EE) atomicAdd(&g_deg[dst[e]], 1);
}

__global__ void scan_kernel() {
    __shared__ int ssum[1024];
    int tid = threadIdx.x;
    int local[10];
    int s = 0;
#pragma unroll
    for (int i = 0; i < 10; i++) {
        int idx = tid * 10 + i;
        int v = (idx < NN) ? g_deg[idx] : 0;
        local[i] = s; s += v;
    }
    ssum[tid] = s;
    __syncthreads();
    for (int off = 1; off < 1024; off <<= 1) {
        int v = (tid >= off) ? ssum[tid - off] : 0;
        __syncthreads();
        ssum[tid] += v;
        __syncthreads();
    }
    int base = (tid > 0) ? ssum[tid - 1] : 0;
#pragma unroll
    for (int i = 0; i < 10; i++) {
        int idx = tid * 10 + i;
        if (idx < NN) {
            int rp = base + local[i];
            g_rowptr[idx] = rp; g_cursor[idx] = rp;
            int d = g_deg[idx];
            g_dinv[idx] = (d > 0) ? (1.0f / (float)d) : 0.0f;
        }
    }
    if (tid == 1023) g_rowptr[NN] = ssum[1023];
}

__global__ void fill_kernel(const int* __restrict__ src, const int* __restrict__ dst) {
    int e = blockIdx.x * 256 + threadIdx.x;
    if (e >= EE) return;
    int p = atomicAdd(&g_cursor[dst[e]], 1);
    g_col[p] = src[e];
}

// Transposed+split weight pack: Wt[set][n][k] = M_{k/256}[k%256][scol(n)], n interleaves u/c
__global__ void pack_kernel(int set,
                            const float* __restrict__ Wxs, const float* __restrict__ Wxn,
                            const float* __restrict__ Whs, const float* __restrict__ Whn,
                            const float* __restrict__ bx, const float* __restrict__ bh) {
    int idx = blockIdx.x * 256 + threadIdx.x;
    if (idx >= 512 * 1024) return;
    int n = idx >> 10, k = idx & 1023;
    int kb = k >> 8, kin = k & 255;
    const float* M = (kb == 0) ? Wxs : (kb == 1) ? Wxn : (kb == 2) ? Whs : Whn;
    int f = n >> 1;
    int scol = (n & 1) ? (2 * FF + f) : (FF + f);
    float v = M[kin * (3 * FF) + scol];
    __nv_bfloat16 hi, lo; split_bf16(v, hi, lo);
    size_t o = (size_t)set * (512 * 1024) + idx;
    g_Wthi[o] = hi; g_Wtlo[o] = lo;
    if (k == 0) g_bpack[set * 512 + n] = bx[scol] + bh[scol];
}

__global__ void packO_kernel(const float* __restrict__ outW) {
    int idx = blockIdx.x * 256 + threadIdx.x;
    if (idx >= 256 * 256) return;
    int n = idx >> 8, k = idx & 255;
    __nv_bfloat16 hi, lo; split_bf16(outW[k * 256 + n], hi, lo);
    g_Othi[idx] = hi; g_Otlo[idx] = lo;
}

// ---------------------------------------------------------------------------
// Neighbor-mean aggregation: fp32 gather (2-way unrolled), bf16 hi/lo output
// ---------------------------------------------------------------------------
template <bool WITHX>
__global__ void agg_kernel(const float* __restrict__ xext, int codeInp, int codeH) {
    const float* inp  = srcF32(codeInp, xext);
    const float* hsrc = srcF32(codeH, xext);
    int node = blockIdx.x;
    int f4 = threadIdx.x;  // 0..63
    int e0 = g_rowptr[node], e1 = g_rowptr[node + 1];
    float4 sx0 = make_float4(0.f, 0.f, 0.f, 0.f), sx1 = sx0;
    float4 sh0 = sx0, sh1 = sx0;
    int e = e0;
    for (; e + 1 < e1; e += 2) {
        int s0 = g_col[e], s1 = g_col[e + 1];
        float4 hv0 = ((const float4*)(hsrc + (size_t)s0 * FF))[f4];
        float4 hv1 = ((const float4*)(hsrc + (size_t)s1 * FF))[f4];
        sh0.x += hv0.x; sh0.y += hv0.y; sh0.z += hv0.z; sh0.w += hv0.w;
        sh1.x += hv1.x; sh1.y += hv1.y; sh1.z += hv1.z; sh1.w += hv1.w;
        if (WITHX) {
            float4 xv0 = ((const float4*)(inp + (size_t)s0 * FF))[f4];
            float4 xv1 = ((const float4*)(inp + (size_t)s1 * FF))[f4];
            sx0.x += xv0.x; sx0.y += xv0.y; sx0.z += xv0.z; sx0.w += xv0.w;
            sx1.x += xv1.x; sx1.y += xv1.y; sx1.z += xv1.z; sx1.w += xv1.w;
        }
    }
    if (e < e1) {
        int s0 = g_col[e];
        float4 hv0 = ((const float4*)(hsrc + (size_t)s0 * FF))[f4];
        sh0.x += hv0.x; sh0.y += hv0.y; sh0.z += hv0.z; sh0.w += hv0.w;
        if (WITHX) {
            float4 xv0 = ((const float4*)(inp + (size_t)s0 * FF))[f4];
            sx0.x += xv0.x; sx0.y += xv0.y; sx0.z += xv0.z; sx0.w += xv0.w;
        }
    }
    float di = g_dinv[node];
    size_t base = (size_t)node * FF + f4 * 4;
    float vh[4] = {(sh0.x + sh1.x) * di, (sh0.y + sh1.y) * di,
                   (sh0.z + sh1.z) * di, (sh0.w + sh1.w) * di};
#pragma unroll
    for (int i = 0; i < 4; i++) {
        __nv_bfloat16 hi, lo; split_bf16(vh[i], hi, lo);
        g_ahhi[base + i] = hi; g_ahlo[base + i] = lo;
    }
    if (WITHX) {
        float vx[4] = {(sx0.x + sx1.x) * di, (sx0.y + sx1.y) * di,
                       (sx0.z + sx1.z) * di, (sx0.w + sx1.w) * di};
#pragma unroll
        for (int i = 0; i < 4; i++) {
            __nv_bfloat16 hi, lo; split_bf16(vx[i], hi, lo);
            g_axhi[base + i] = hi; g_axlo[base + i] = lo;
        }
    }
}

// ---------------------------------------------------------------------------
// bf16 mma.sync GEMM (3-product split) with fused GRU / bias epilogue.
//   C[128, 128] per CTA; K-chunk 64/stage; 3-buffer 1-ahead cp.async pipeline,
//   single __syncthreads per stage.
// ---------------------------------------------------------------------------
#define SROW 72                       // smem row stride in bf16 (144 B): conflict-free
#define STAGE_BYTES (128 * SROW * 2)  // 18432 per matrix
#define BUF_BYTES   (2 * STAGE_BYTES) // A + B per stage
#define SMEM_TOTAL  (3 * BUF_BYTES)   // 110592

__global__ __launch_bounds__(256, 2)
void mma_gemm(int4 codes, int nblk, int xoff_i,
              int wset, int kofs,
              const float* __restrict__ bExt,
              int holdIdx, int outIdx, float* __restrict__ outExt,
              int gruFlag) {
    extern __shared__ __align__(16) char dsm[];

    const int tid = threadIdx.x;
    const int lane = tid & 31;
    const int wid = tid >> 5;
    const int warp_m = wid & 1;        // 0..1 (64 rows)
    const int warp_n = wid >> 1;       // 0..3 (32 cols)
    const int bm = blockIdx.x * 128;
    const int n0 = blockIdx.y * 128;
    const size_t xoff = (size_t)xoff_i * NF;

    const __nv_bfloat16* Ahi[4];
    const __nv_bfloat16* Alo[4];
    {
        int ca[4] = {codes.x, codes.y, codes.z, codes.w};
#pragma unroll
        for (int b = 0; b < 4; b++) { Ahi[b] = srcHi(ca[b], xoff); Alo[b] = srcLo(ca[b], xoff); }
    }
    const __nv_bfloat16* Whi;
    const __nv_bfloat16* Wlo;
    int kstride;
    const float* bias;
    if (wset >= 0) {
        Whi = g_Wthi + (size_t)wset * (512 * 1024) + kofs;
        Wlo = g_Wtlo + (size_t)wset * (512 * 1024) + kofs;
        kstride = 1024;
        bias = g_bpack + wset * 512;
    } else {
        Whi = g_Othi; Wlo = g_Otlo; kstride = 256; bias = bExt;
    }
    const float* hold = g_h + (size_t)((holdIdx >= 0) ? holdIdx : 0) * NF;

    const uint32_t sBase = smem_u32(dsm);

    float acc[4][4][4];
#pragma unroll
    for (int mi = 0; mi < 4; mi++)
#pragma unroll
        for (int ni = 0; ni < 4; ni++)
#pragma unroll
            for (int v = 0; v < 4; v++) acc[mi][ni][v] = 0.0f;

    const int S = 3 * nblk * 4;        // K-chunk = 64

    // per-stage loads: 1024 16B-chunks per matrix, 4 per thread each
    auto issue = [&](int s, int b) {
        const int pass = s / (nblk * 4);
        const int rem  = s - pass * (nblk * 4);
        const int blk  = rem >> 2;
        const int kc   = rem & 3;      // 64-col chunk within 256-K block
        const __nv_bfloat16* Asrc = (pass == 1) ? Alo[blk] : Ahi[blk];
        const __nv_bfloat16* Bsrc = (pass == 2) ? Wlo : Whi;
        const uint32_t aBase = sBase + b * BUF_BYTES;
        const uint32_t bBase = aBase + STAGE_BYTES;
#pragma unroll
        for (int j = 0; j < 4; j++) {
            int c = tid + j * 256;     // 0..1023
            int row = c >> 3, seg = c & 7;
            uint32_t so = row * (SROW * 2) + seg * 16;
            cpasync16(aBase + so, Asrc + ((size_t)(bm + row) << 8) + kc * 64 + seg * 8);
            cpasync16(bBase + so, Bsrc + (size_t)(n0 + row) * kstride + blk * 256 + kc * 64 + seg * 8);
        }
    };

    // ldmatrix per-lane address pieces
    const int selA = lane >> 3;
    const int rowA = (selA & 1) * 8 + (lane & 7);
    const int kpaA = (selA >> 1) * 8;
    const int rowB = lane & 7;
    const int kpaB = ((lane >> 3) & 1) * 8;

    issue(0, 0);
    CP_COMMIT();

    for (int s = 0; s < S; s++) {
        const int b = s - (s / 3) * 3;             // s % 3
        if (s + 1 < S) {
            int b1 = (s + 1) - ((s + 1) / 3) * 3;
            issue(s + 1, b1);
            CP_COMMIT();
            CP_WAIT1();
        } else {
            CP_WAIT0();
        }
        __syncthreads();

        const uint32_t aBase = sBase + b * BUF_BYTES;
        const uint32_t bBase = aBase + STAGE_BYTES;
#pragma unroll
        for (int kh = 0; kh < 4; kh++) {
            uint32_t af[4][4], bf[4][2];
#pragma unroll
            for (int mi = 0; mi < 4; mi++) {
                uint32_t addr = aBase +
                    (warp_m * 64 + mi * 16 + rowA) * (SROW * 2) + (kh * 16 + kpaA) * 2;
                LDSM4(af[mi][0], af[mi][1], af[mi][2], af[mi][3], addr);
            }
#pragma unroll
            for (int ni = 0; ni < 4; ni++) {
                uint32_t addr = bBase +
                    (warp_n * 32 + ni * 8 + rowB) * (SROW * 2) + (kh * 16 + kpaB) * 2;
                LDSM2(bf[ni][0], bf[ni][1], addr);
            }
#pragma unroll
            for (int mi = 0; mi < 4; mi++)
#pragma unroll
                for (int ni = 0; ni < 4; ni++)
                    MMA16816(acc[mi][ni], af[mi][0], af[mi][1], af[mi][2], af[mi][3],
                             bf[ni][0], bf[ni][1]);
        }
    }

    // Epilogue straight from registers
    const int r4 = lane >> 2;
    const int cp2 = (lane & 3) * 2;
#pragma unroll
    for (int mi = 0; mi < 4; mi++) {
        int row0 = bm + warp_m * 64 + mi * 16 + r4;
#pragma unroll
        for (int ni = 0; ni < 4; ni++) {
            int colp = n0 + warp_n * 32 + ni * 8 + cp2;
#pragma unroll
            for (int half = 0; half < 2; half++) {
                int r = row0 + half * 8;
                if (r >= NN) continue;
                float v0 = acc[mi][ni][half * 2 + 0];
                float v1 = acc[mi][ni][half * 2 + 1];
                if (gruFlag) {
                    float up = v0 + bias[colp];
                    float cc = tanhf(v1 + bias[colp + 1]);
                    float u  = 1.0f / (1.0f + expf(-up));
                    int f = colp >> 1;
                    float hv = hold[(size_t)r * FF + f];
                    float hn = u * hv + (1.0f - u) * cc;
                    size_t o = (size_t)outIdx * NF + (size_t)r * FF + f;
                    g_h[o] = hn;
                    __nv_bfloat16 hi, lo; split_bf16(hn, hi, lo);
                    g_hhi[o] = hi; g_hlo[o] = lo;
                } else {
                    size_t o = (size_t)r * FF + colp;
                    outExt[o]     = v0 + bias[colp];
                    outExt[o + 1] = v1 + bias[colp + 1];
                }
            }
        }
    }
}

// ---------------------------------------------------------------------------
// Host orchestration (graph-capturable)
// ---------------------------------------------------------------------------
extern "C" void kernel_launch(void* const* d_in, const int* in_sizes, int n_in,
                              void* d_out, int out_size) {
    const float* x    = (const float*)d_in[0];
    const int*   src  = (const int*)d_in[1];
    const int*   dst  = (const int*)d_in[2];
    const float* eWxs = (const float*)d_in[3];
    const float* eWxn = (const float*)d_in[4];
    const float* ebx  = (const float*)d_in[5];
    const float* eWhs = (const float*)d_in[6];
    const float* eWhn = (const float*)d_in[7];
    const float* ebh  = (const float*)d_in[8];
    const float* dWxs = (const float*)d_in[9];
    const float* dWxn = (const float*)d_in[10];
    const float* dbx  = (const float*)d_in[11];
    const float* dWhs = (const float*)d_in[12];
    const float* dWhn = (const float*)d_in[13];
    const float* dbh  = (const float*)d_in[14];
    const float* outW = (const float*)d_in[15];
    const float* outb = (const float*)d_in[16];
    float* out = (float*)d_out;

    cudaFuncSetAttribute(mma_gemm, cudaFuncAttributeMaxDynamicSharedMemorySize, SMEM_TOTAL);

    const int F3F = FF * 3 * FF;

    zero_kernel<<<(4 * NF + PAD + 255) / 256, 256>>>();
    xconv_kernel<<<(12 * NF + 255) / 256, 256>>>(x);
    deg_kernel<<<(EE + 255) / 256, 256>>>(dst);
    scan_kernel<<<1, 1024>>>();
    fill_kernel<<<(EE + 255) / 256, 256>>>(src, dst);
    pack_kernel<<<(512 * 1024 + 255) / 256, 256>>>(0, eWxs, eWxn, eWhs, eWhn, ebx, ebh);
    pack_kernel<<<(512 * 1024 + 255) / 256, 256>>>(1, eWxs + F3F, eWxn + F3F, eWhs + F3F,
                                                   eWhn + F3F, ebx + 3 * FF, ebh + 3 * FF);
    pack_kernel<<<(512 * 1024 + 255) / 256, 256>>>(2, dWxs, dWxn, dWhs, dWhn, dbx, dbh);
    pack_kernel<<<(512 * 1024 + 255) / 256, 256>>>(3, dWxs + F3F, dWxn + F3F, dWhs + F3F,
                                                   dWhn + F3F, dbx + 3 * FF, dbh + 3 * FF);
    packO_kernel<<<(256 * 256 + 255) / 256, 256>>>(outW);

    dim3 gg(79, 4);   // GRU GEMM: 512 cols
    dim3 og(79, 2);   // out-proj: 256 cols
    int cur0 = 0, cur1 = 0;
    auto HI = [](int buf, int layer) { return buf * 2 + layer; };

    // ---- Encoder ----
    for (int t = 0; t < TT; t++) {
        const float* xt = x + (size_t)t * NF;
        agg_kernel<true><<<NN, 64>>>(xt, 6, HI(cur0, 0));
        mma_gemm<<<gg, 256, SMEM_TOTAL>>>(make_int4(6, 4, HI(cur0, 0), 5), 4, t,
                                          0, 0, nullptr, HI(cur0, 0), HI(1 - cur0, 0), nullptr, 1);
        cur0 ^= 1;
        agg_kernel<true><<<NN, 64>>>(nullptr, HI(cur0, 0), HI(cur1, 1));
        mma_gemm<<<gg, 256, SMEM_TOTAL>>>(make_int4(HI(cur0, 0), 4, HI(cur1, 1), 5), 4, 0,
                                          1, 0, nullptr, HI(cur1, 1), HI(1 - cur1, 1), nullptr, 1);
        cur1 ^= 1;
    }

    // ---- Decoder ----
    for (int t = 0; t < TT; t++) {
        agg_kernel<false><<<NN, 64>>>(nullptr, 0, HI(cur0, 0));
        mma_gemm<<<gg, 256, SMEM_TOTAL>>>(make_int4(HI(cur0, 0), 5, 0, 0), 2, 0,
                                          2, 512, nullptr, HI(cur0, 0), HI(1 - cur0, 0), nullptr, 1);
        cur0 ^= 1;
        agg_kernel<true><<<NN, 64>>>(nullptr, HI(cur0, 0), HI(cur1, 1));
        mma_gemm<<<gg, 256, SMEM_TOTAL>>>(make_int4(HI(cur0, 0), 4, HI(cur1, 1), 5), 4, 0,
                                          3, 0, nullptr, HI(cur1, 1), HI(1 - cur1, 1), nullptr, 1);
        cur1 ^= 1;
        mma_gemm<<<og, 256, SMEM_TOTAL>>>(make_int4(HI(cur1, 1), 0, 0, 0), 1, 0,
                                          -1, 0, outb, -1, -1, out + (size_t)t * NF, 0);
    }
}